// round 3
// baseline (speedup 1.0000x reference)
#include <cuda_runtime.h>
#include <math.h>

// Problem constants
#define T_SEQ   1024
#define BATCH   256
#define IN_DIM  64
#define HID     512
#define NCLS    10
#define KTOT    (HID + IN_DIM)      // 576: Whh rows then Whx rows
#define GROUPS  16                  // batch groups
#define CPG     8                   // CTAs per group (j-split)
#define RPG     16                  // batch rows per group
#define JSL     64                  // j columns per CTA
#define NTHR    256

// Persistent scratch (no allocations allowed): ping-pong hidden state + group barriers
__device__ float             g_hbuf[2][BATCH * HID];
__device__ unsigned          g_cnt[GROUPS];
__device__ volatile unsigned g_sense[GROUPS];

// ---- packed fp32x2 helpers (FFMA2 path on sm_103a) ----
__device__ __forceinline__ void ffma2(unsigned long long& d,
                                      unsigned long long a,
                                      unsigned long long b) {
    asm("fma.rn.f32x2 %0, %1, %2, %0;" : "+l"(d) : "l"(a), "l"(b));
}
__device__ __forceinline__ unsigned long long fadd2(unsigned long long a,
                                                    unsigned long long b) {
    unsigned long long d;
    asm("add.rn.f32x2 %0, %1, %2;" : "=l"(d) : "l"(a), "l"(b));
    return d;
}
__device__ __forceinline__ float2 unpack2(unsigned long long a) {
    float2 r;
    asm("mov.b64 {%0,%1}, %2;" : "=f"(r.x), "=f"(r.y) : "l"(a));
    return r;
}
__device__ __forceinline__ unsigned long long pack2(float x, float y) {
    unsigned long long d;
    asm("mov.b64 %0, {%1,%2};" : "=l"(d) : "f"(x), "f"(y));
    return d;
}

// SMEM layout (dynamic):
//   W2  : KTOT x JSL weights, interleaved: (k,j) -> (k>>1)*128 + (j>>1)*4 + (k&1)*2 + (j&1)
//         => one 16B load gives {W[k][j0],W[k][j1],W[k+1][j0],W[k+1][j1]} for a j-pair
//   hs2 : RPG x KTOT, each value DUPLICATED: (r,k) -> r*1152 + 2k + {0,1} = (h,h)
//         => one 16B load gives {(h[k],h[k]),(h[k+1],h[k+1])}
//   bh_s: 64 bias values
#define W2_FLOATS   (KTOT * JSL)          // 36864
#define HS2_FLOATS  (RPG * KTOT * 2)      // 18432
#define SMEM_FLOATS (W2_FLOATS + HS2_FLOATS + JSL)
#define HROWF       (KTOT * 2)            // 1152 floats per hs2 row

__global__ __launch_bounds__(NTHR, 1)
void rnn_persistent(const float* __restrict__ x,   const float* __restrict__ Whx,
                    const float* __restrict__ Whh, const float* __restrict__ Wph,
                    const float* __restrict__ bh,  const float* __restrict__ bp,
                    float* __restrict__ out)
{
    extern __shared__ float smem[];
    float* W2   = smem;
    float* hs2  = smem + W2_FLOATS;
    float* bh_s = hs2 + HS2_FLOATS;

    const int tid  = threadIdx.x;
    const int g    = blockIdx.x / CPG;     // batch group
    const int jc   = blockIdx.x % CPG;     // j-slice index
    const int jb   = jc * JSL;             // global j base
    const int row0 = g * RPG;              // global batch row base

    // ---- one-time weight load into interleaved SMEM layout ----
    for (int idx = tid; idx < KTOT * JSL; idx += NTHR) {
        int k = idx >> 6, j = idx & 63;
        float w = (k < HID) ? Whh[k * HID + jb + j]
                            : Whx[(k - HID) * HID + jb + j];
        W2[(k >> 1) * 128 + (j >> 1) * 4 + (k & 1) * 2 + (j & 1)] = w;
    }
    if (tid < JSL) bh_s[tid] = bh[jb + tid];
    __syncthreads();

    // thread tile: 2 batch rows x 1 j-pair (4 outputs)
    const int jp = tid & 31;          // j-pair index: j0 = 2*jp, j1 = 2*jp+1
    const int rp = tid >> 5;          // row-pair index
    const int r0 = rp * 2, r1 = r0 + 1;

    const ulonglong2* h0p = (const ulonglong2*)(hs2 + r0 * HROWF);
    const ulonglong2* h1p = (const ulonglong2*)(hs2 + r1 * HROWF);
    const ulonglong2* wp  = (const ulonglong2*)W2 + jp;   // stride 32 per k-pair

    const float2 b2 = *(const float2*)(bh_s + 2 * jp);
    const unsigned long long bias = pack2(b2.x, b2.y);

    unsigned local_sense = 0;

    for (int t = 0; t < T_SEQ; ++t) {
        const int br = t & 1, bw = br ^ 1;

        // ---- stage h (duplicated) into SMEM ----
        if (t == 0) {
            const float4 z = make_float4(0.f, 0.f, 0.f, 0.f);
            for (int i = tid; i < RPG * (HID / 4); i += NTHR) {
                int r = i >> 7, kq = i & 127;
                float4* d = (float4*)(hs2 + r * HROWF + kq * 8);
                d[0] = z; d[1] = z;
            }
        } else {
            const float4* src = (const float4*)g_hbuf[br];
            for (int i = tid; i < RPG * (HID / 4); i += NTHR) {
                int r = i >> 7, kq = i & 127;
                float4 v = __ldcg(src + (row0 + r) * (HID / 4) + kq);
                float4* d = (float4*)(hs2 + r * HROWF + kq * 8);
                d[0] = make_float4(v.x, v.x, v.y, v.y);
                d[1] = make_float4(v.z, v.z, v.w, v.w);
            }
        }
        // ---- stage x_t (duplicated) into SMEM tail rows ----
        for (int i = tid; i < RPG * (IN_DIM / 4); i += NTHR) {
            int r = i >> 4, q = i & 15;
            float4 v = __ldg((const float4*)(x + (size_t)(row0 + r) * (T_SEQ * IN_DIM)
                                               + t * IN_DIM) + q);
            float4* d = (float4*)(hs2 + r * HROWF + (HID + q * 4) * 2);
            d[0] = make_float4(v.x, v.x, v.y, v.y);
            d[1] = make_float4(v.z, v.z, v.w, v.w);
        }
        __syncthreads();

        // ---- GEMM slice: out[r0/r1][j-pair] over k = 0..575, packed FFMA2 ----
        unsigned long long a0e = bias, a0o = 0ull, a1e = bias, a1o = 0ull;
        #pragma unroll 2
        for (int kq = 0; kq < KTOT / 8; ++kq) {          // 8 k per iteration
            ulonglong2 wA = wp[(4 * kq + 0) * 32];
            ulonglong2 wB = wp[(4 * kq + 1) * 32];
            ulonglong2 wC = wp[(4 * kq + 2) * 32];
            ulonglong2 wD = wp[(4 * kq + 3) * 32];
            ulonglong2 hA0 = h0p[4 * kq + 0], hB0 = h0p[4 * kq + 1];
            ulonglong2 hC0 = h0p[4 * kq + 2], hD0 = h0p[4 * kq + 3];
            ulonglong2 hA1 = h1p[4 * kq + 0], hB1 = h1p[4 * kq + 1];
            ulonglong2 hC1 = h1p[4 * kq + 2], hD1 = h1p[4 * kq + 3];

            ffma2(a0e, hA0.x, wA.x); ffma2(a1e, hA1.x, wA.x);
            ffma2(a0o, hA0.y, wA.y); ffma2(a1o, hA1.y, wA.y);
            ffma2(a0e, hB0.x, wB.x); ffma2(a1e, hB1.x, wB.x);
            ffma2(a0o, hB0.y, wB.y); ffma2(a1o, hB1.y, wB.y);
            ffma2(a0e, hC0.x, wC.x); ffma2(a1e, hC1.x, wC.x);
            ffma2(a0o, hC0.y, wC.y); ffma2(a1o, hC1.y, wC.y);
            ffma2(a0e, hD0.x, wD.x); ffma2(a1e, hD1.x, wD.x);
            ffma2(a0o, hD0.y, wD.y); ffma2(a1o, hD1.y, wD.y);
        }

        float2 o0 = unpack2(fadd2(a0e, a0o));
        float2 o1 = unpack2(fadd2(a1e, a1o));
        float2 s0 = make_float2(tanhf(o0.x), tanhf(o0.y));
        float2 s1 = make_float2(tanhf(o1.x), tanhf(o1.y));
        __stcg((float2*)(g_hbuf[bw] + (row0 + r0) * HID + jb + 2 * jp), s0);
        __stcg((float2*)(g_hbuf[bw] + (row0 + r1) * HID + jb + 2 * jp), s1);

        // ---- per-group barrier (8 CTAs), sense-reversing, release/acquire ----
        __syncthreads();                       // all stores issued (CTA scope)
        if (tid == 0) {
            __threadfence();                   // cumulative release (gpu scope)
            unsigned ls = local_sense ^ 1;
            if (atomicAdd(&g_cnt[g], 1u) == CPG - 1) {
                atomicExch(&g_cnt[g], 0u);
                __threadfence();
                g_sense[g] = ls;
            } else {
                while (g_sense[g] != ls) { }
            }
            __threadfence();                   // acquire side
        }
        local_sense ^= 1;
        __syncthreads();
    }

    // ---- final projection p = h_final @ Wph + bp ; h_final is in g_hbuf[0] ----
    if (jc == 0) {
        for (int o = tid; o < RPG * NCLS; o += NTHR) {
            int r = o / NCLS, c = o % NCLS;
            const float4* hrow = (const float4*)(g_hbuf[0] + (row0 + r) * HID);
            float a0 = 0.f, a1 = 0.f, a2 = 0.f, a3 = 0.f;
            #pragma unroll 4
            for (int kq = 0; kq < HID / 4; ++kq) {
                float4 hv = __ldcg(hrow + kq);
                a0 += hv.x * __ldg(Wph + (4 * kq + 0) * NCLS + c);
                a1 += hv.y * __ldg(Wph + (4 * kq + 1) * NCLS + c);
                a2 += hv.z * __ldg(Wph + (4 * kq + 2) * NCLS + c);
                a3 += hv.w * __ldg(Wph + (4 * kq + 3) * NCLS + c);
            }
            out[(row0 + r) * NCLS + c] = (a0 + a1) + (a2 + a3) + __ldg(bp + c);
        }
    }
}

extern "C" void kernel_launch(void* const* d_in, const int* in_sizes, int n_in,
                              void* d_out, int out_size) {
    const float* x   = (const float*)d_in[0];
    const float* Whx = (const float*)d_in[1];
    const float* Whh = (const float*)d_in[2];
    const float* Wph = (const float*)d_in[3];
    const float* bh  = (const float*)d_in[4];
    const float* bp  = (const float*)d_in[5];

    const size_t smem_bytes = (size_t)SMEM_FLOATS * sizeof(float);   // 221440 B
    cudaFuncSetAttribute(rnn_persistent,
                         cudaFuncAttributeMaxDynamicSharedMemorySize,
                         (int)smem_bytes);
    rnn_persistent<<<GROUPS * CPG, NTHR, smem_bytes>>>(
        x, Whx, Whh, Wph, bh, bp, (float*)d_out);
}

// round 5
// speedup vs baseline: 1.6975x; 1.6975x over previous
#include <cuda_runtime.h>
#include <math.h>

#define T_SEQ   1024
#define BATCH   256
#define IN_DIM  64
#define HID     512
#define NCLS    10
#define KTOT    (HID + IN_DIM)      // 576
#define GROUPS  16                  // batch groups
#define CPG     8                   // CTAs per group (j-split)
#define RPG     16                  // batch rows per group
#define JSL     64                  // j columns per CTA
#define NTHR    256
#define NSLC    16                  // k-slices (split-k factor)
#define KE      (KTOT / NSLC)       // 36 k per slice
#define KP      (KE / 2)            // 18 k-pairs per slice
#define JPT     4                   // j columns per thread

__device__ float             g_hbuf[2][BATCH * HID];
__device__ unsigned          g_cnt[GROUPS];
__device__ volatile unsigned g_sense[GROUPS];

__device__ __forceinline__ void ffma2(unsigned long long& d,
                                      unsigned long long a,
                                      unsigned long long b) {
    asm("fma.rn.f32x2 %0, %1, %2, %0;" : "+l"(d) : "l"(a), "l"(b));
}
__device__ __forceinline__ float2 unpack2(unsigned long long a) {
    float2 r;
    asm("mov.b64 {%0,%1}, %2;" : "=f"(r.x), "=f"(r.y) : "l"(a));
    return r;
}
__device__ __forceinline__ unsigned long long pack2(float x, float y) {
    unsigned long long d;
    asm("mov.b64 %0, {%1,%2};" : "=l"(d) : "f"(x), "f"(y));
    return d;
}

__global__ __launch_bounds__(NTHR, 1)
void rnn_regw(const float* __restrict__ x,   const float* __restrict__ Whx,
              const float* __restrict__ Whh, const float* __restrict__ Wph,
              const float* __restrict__ bh,  const float* __restrict__ bp,
              float* __restrict__ out)
{
    extern __shared__ float hs[];           // RPG x KTOT plain h||x staging

    const int tid  = threadIdx.x;
    const int g    = blockIdx.x / CPG;      // batch group
    const int jc   = blockIdx.x % CPG;      // j-slice index
    const int jb   = jc * JSL;              // global j base for this CTA
    const int row0 = g * RPG;               // global batch row base

    const int ks = tid & (NSLC - 1);        // k-slice 0..15
    const int jq = tid >> 4;                // j-quad 0..15
    const int j0 = jb + jq * JPT;           // this thread's 4 j columns

    // ---- one-time: weights into registers, packed over k-pairs ----
    // wreg[kp][jj] = (W[k][j0+jj], W[k+1][j0+jj]),  k = ks*KE + 2*kp
    unsigned long long wreg[KP][JPT];
    #pragma unroll
    for (int kp = 0; kp < KP; ++kp) {
        const int k = ks * KE + 2 * kp;
        #pragma unroll
        for (int jj = 0; jj < JPT; ++jj) {
            float wa = (k     < HID) ? __ldg(Whh + k * HID + j0 + jj)
                                     : __ldg(Whx + (k - HID) * HID + j0 + jj);
            float wb = (k + 1 < HID) ? __ldg(Whh + (k + 1) * HID + j0 + jj)
                                     : __ldg(Whx + (k + 1 - HID) * HID + j0 + jj);
            wreg[kp][jj] = pack2(wa, wb);
        }
    }
    const float4 bias4 = *(const float4*)(bh + j0);

    unsigned local_sense = 0;

    for (int t = 0; t < T_SEQ; ++t) {
        const int br = t & 1, bw = br ^ 1;

        // ---- stage h (plain) into SMEM ----
        if (t == 0) {
            const float4 z = make_float4(0.f, 0.f, 0.f, 0.f);
            #pragma unroll
            for (int u = 0; u < 8; ++u) {
                int i = tid + u * NTHR;                 // 0..2047
                int r = i >> 7, c = i & 127;            // 128 float4 per row
                ((float4*)(hs + r * KTOT))[c] = z;
            }
        } else {
            const float4* src = (const float4*)g_hbuf[br];
            #pragma unroll
            for (int u = 0; u < 8; ++u) {
                int i = tid + u * NTHR;
                int r = i >> 7, c = i & 127;
                ((float4*)(hs + r * KTOT))[c] =
                    __ldcg(src + (row0 + r) * (HID / 4) + c);
            }
        }
        // ---- stage x_t into SMEM tail ----
        {
            int r = tid >> 4, q = tid & 15;             // 16 float4 per row
            const float4* xp = (const float4*)(x + (size_t)(row0 + r) * (T_SEQ * IN_DIM)
                                                 + (size_t)t * IN_DIM);
            ((float4*)(hs + r * KTOT + HID))[q] = __ldg(xp + q);
        }
        __syncthreads();

        // ---- 4 passes of 4 rows: k-packed FFMA2 against register weights ----
        for (int p = 0; p < 4; ++p) {
            unsigned long long acc[4][JPT];
            #pragma unroll
            for (int rr = 0; rr < 4; ++rr)
                #pragma unroll
                for (int jj = 0; jj < JPT; ++jj) acc[rr][jj] = 0ull;

            #pragma unroll
            for (int rr = 0; rr < 4; ++rr) {
                const ulonglong2* hp =
                    (const ulonglong2*)(hs + (p * 4 + rr) * KTOT + ks * KE);
                #pragma unroll
                for (int i = 0; i < 9; ++i) {           // 9 x 16B = 36 h values
                    ulonglong2 hv = hp[i];
                    #pragma unroll
                    for (int jj = 0; jj < JPT; ++jj)
                        ffma2(acc[rr][jj], hv.x, wreg[2 * i][jj]);
                    #pragma unroll
                    for (int jj = 0; jj < JPT; ++jj)
                        ffma2(acc[rr][jj], hv.y, wreg[2 * i + 1][jj]);
                }
            }

            // collapse k-pair lanes, then butterfly-reduce over the 16 k-slices
            float v[4][JPT];
            #pragma unroll
            for (int rr = 0; rr < 4; ++rr)
                #pragma unroll
                for (int jj = 0; jj < JPT; ++jj) {
                    float2 u = unpack2(acc[rr][jj]);
                    v[rr][jj] = u.x + u.y;
                }
            #pragma unroll
            for (int m = 1; m < NSLC; m <<= 1)
                #pragma unroll
                for (int rr = 0; rr < 4; ++rr)
                    #pragma unroll
                    for (int jj = 0; jj < JPT; ++jj)
                        v[rr][jj] += __shfl_xor_sync(0xffffffffu, v[rr][jj], m, 32);

            // lanes ks=0..3 each take one row (compile-time register select)
            float4 o; bool act = false;
            if      (ks == 0) { o = make_float4(v[0][0], v[0][1], v[0][2], v[0][3]); act = true; }
            else if (ks == 1) { o = make_float4(v[1][0], v[1][1], v[1][2], v[1][3]); act = true; }
            else if (ks == 2) { o = make_float4(v[2][0], v[2][1], v[2][2], v[2][3]); act = true; }
            else if (ks == 3) { o = make_float4(v[3][0], v[3][1], v[3][2], v[3][3]); act = true; }
            if (act) {
                o.x = tanhf(o.x + bias4.x);
                o.y = tanhf(o.y + bias4.y);
                o.z = tanhf(o.z + bias4.z);
                o.w = tanhf(o.w + bias4.w);
                __stcg((float4*)(g_hbuf[bw] + (size_t)(row0 + p * 4 + ks) * HID + j0), o);
            }
        }

        // ---- per-group barrier (8 CTAs), sense-reversing ----
        __syncthreads();
        if (tid == 0) {
            __threadfence();
            unsigned ls = local_sense ^ 1;
            if (atomicAdd(&g_cnt[g], 1u) == CPG - 1) {
                atomicExch(&g_cnt[g], 0u);
                __threadfence();
                g_sense[g] = ls;
            } else {
                while (g_sense[g] != ls) { }
            }
            __threadfence();
        }
        local_sense ^= 1;
        __syncthreads();
    }

    // ---- final projection p = h_final @ Wph + bp ; h_final in g_hbuf[0] ----
    if (jc == 0) {
        for (int o = tid; o < RPG * NCLS; o += NTHR) {
            int r = o / NCLS, c = o % NCLS;
            const float4* hrow = (const float4*)(g_hbuf[0] + (row0 + r) * HID);
            float a0 = 0.f, a1 = 0.f, a2 = 0.f, a3 = 0.f;
            #pragma unroll 4
            for (int kq = 0; kq < HID / 4; ++kq) {
                float4 hv = __ldcg(hrow + kq);
                a0 += hv.x * __ldg(Wph + (4 * kq + 0) * NCLS + c);
                a1 += hv.y * __ldg(Wph + (4 * kq + 1) * NCLS + c);
                a2 += hv.z * __ldg(Wph + (4 * kq + 2) * NCLS + c);
                a3 += hv.w * __ldg(Wph + (4 * kq + 3) * NCLS + c);
            }
            out[(row0 + r) * NCLS + c] = (a0 + a1) + (a2 + a3) + __ldg(bp + c);
        }
    }
}

extern "C" void kernel_launch(void* const* d_in, const int* in_sizes, int n_in,
                              void* d_out, int out_size) {
    const float* x   = (const float*)d_in[0];
    const float* Whx = (const float*)d_in[1];
    const float* Whh = (const float*)d_in[2];
    const float* Wph = (const float*)d_in[3];
    const float* bh  = (const float*)d_in[4];
    const float* bp  = (const float*)d_in[5];

    const size_t smem_bytes = (size_t)RPG * KTOT * sizeof(float);   // 36864 B
    rnn_regw<<<GROUPS * CPG, NTHR, smem_bytes>>>(
        x, Whx, Whh, Wph, bh, bp, (float*)d_out);
}